// round 5
// baseline (speedup 1.0000x reference)
#include <cuda_runtime.h>

// Problem constants (B=256, S=1024, H=128)
#define SEQ   1024
#define HID   128
#define NMV   384             // matvec threads: one per W_hh row (12 warps)
#define NGT   32              // gate warp (warp 12): 4 hidden units / thread
#define NTOT  (NMV + NGT)     // 416 threads -> reg cap 157/thread
#define BPC   2               // batches per CTA
#define NCTA  128             // 128 CTAs -> single wave on 148 SMs

// Named barriers: 1,2 = "gh ready" (batch 0/1); 3,4 = "h ready" (batch 0/1)
#define BAR_SYNC(id)   asm volatile("bar.sync %0, %1;"   :: "n"(id), "n"(NTOT) : "memory")
#define BAR_ARRIVE(id) asm volatile("bar.arrive %0, %1;" :: "n"(id), "n"(NTOT) : "memory")

// Packed 2xfp32 FMA (Blackwell f32x2; ptxas won't auto-fuse from C++)
__device__ __forceinline__ unsigned long long ffma2(unsigned long long a,
                                                    unsigned long long b,
                                                    unsigned long long c) {
    unsigned long long d;
    asm("fma.rn.f32x2 %0, %1, %2, %3;" : "=l"(d) : "l"(a), "l"(b), "l"(c));
    return d;
}

__device__ __forceinline__ float2 unpack_f32x2(unsigned long long v) {
    float2 f;
    asm("mov.b64 {%0, %1}, %2;" : "=f"(f.x), "=f"(f.y) : "l"(v));
    return f;
}

__device__ __forceinline__ float fsig(float x) {
    return __fdividef(1.0f, 1.0f + __expf(-x));   // EX2 + RCP, rel err ~1e-6
}
__device__ __forceinline__ float ftanh(float x) {
    float ax = fabsf(x);
    float e  = __expf(-2.0f * ax);
    float r  = __fdividef(1.0f - e, 1.0f + e);
    return copysignf(r, x);
}

__global__ void __launch_bounds__(NTOT, 1)
gru_fused_kernel(const float* __restrict__ x,     // [B, S]
                 const float* __restrict__ w_ih,  // [3H]
                 const float* __restrict__ w_hh,  // [3H, H]
                 const float* __restrict__ b_ih,  // [3H]
                 const float* __restrict__ b_hh,  // [3H]
                 const float* __restrict__ w_fc,  // [H]
                 const float* __restrict__ b_fc,  // [1]
                 float* __restrict__ out)         // [B]
{
    __shared__ __align__(16) float x_sh[BPC][SEQ];       // 8 KB
    __shared__ __align__(16) float h_sh[BPC][HID];       // hidden states
    __shared__ __align__(16) float gh_sh[BPC][3 * HID];  // raw W_hh.h dots

    const int t  = threadIdx.x;
    const int b0 = blockIdx.x * BPC;

    // stage x for both batches (contiguous rows)
    for (int i = t; i < BPC * SEQ; i += NTOT)
        (&x_sh[0][0])[i] = x[b0 * SEQ + i];
    if (t < BPC * HID)
        (&h_sh[0][0])[t] = 0.0f;

    unsigned long long w2[HID / 2];   // lives only on the matvec path
    if (t < NMV) {
        const ulonglong2* wr = reinterpret_cast<const ulonglong2*>(w_hh + t * HID);
        #pragma unroll
        for (int i = 0; i < HID / 4; i++) {
            ulonglong2 v = wr[i];
            w2[2 * i]     = v.x;
            w2[2 * i + 1] = v.y;
        }
    }
    __syncthreads();

    if (t < NMV) {
        // ================= matvec engine (12 warps) =================
        #define MATVEC_PHASE(P)                                                   \
            do {                                                                  \
                const ulonglong2* hp =                                            \
                    reinterpret_cast<const ulonglong2*>(h_sh[P]);                 \
                unsigned long long a0 = 0ull, a1 = 0ull;                          \
                _Pragma("unroll")                                                 \
                for (int i = 0; i < HID / 4; i++) {                               \
                    ulonglong2 v = hp[i];                                         \
                    a0 = ffma2(w2[2 * i],     v.x, a0);                           \
                    a1 = ffma2(w2[2 * i + 1], v.y, a1);                           \
                }                                                                 \
                float2 f0 = unpack_f32x2(a0), f1 = unpack_f32x2(a1);              \
                gh_sh[P][t] = (f0.x + f0.y) + (f1.x + f1.y);                      \
            } while (0)

        for (int s = 0; s < SEQ; s++) {
            if (s) BAR_SYNC(3);          // h[0] for step s ready
            MATVEC_PHASE(0);
            BAR_ARRIVE(1);               // gh[0] ready
            if (s) BAR_SYNC(4);          // h[1] for step s ready
            MATVEC_PHASE(1);
            BAR_ARRIVE(2);               // gh[1] ready
        }
    } else {
        // ================= gate engine (1 warp, 4 units/thread) =================
        const int j = (t - NMV) * 4;

        float4 Wr = *(const float4*)(w_ih + j);
        float4 Wz = *(const float4*)(w_ih + HID + j);
        float4 Wn = *(const float4*)(w_ih + 2 * HID + j);
        // combined biases for r,z; split for n
        float4 Br, Bz, Bn, Gn;
        {
            float4 bir = *(const float4*)(b_ih + j);
            float4 biz = *(const float4*)(b_ih + HID + j);
            float4 bin = *(const float4*)(b_ih + 2 * HID + j);
            float4 bhr = *(const float4*)(b_hh + j);
            float4 bhz = *(const float4*)(b_hh + HID + j);
            float4 bhn = *(const float4*)(b_hh + 2 * HID + j);
            Br = make_float4(bir.x + bhr.x, bir.y + bhr.y, bir.z + bhr.z, bir.w + bhr.w);
            Bz = make_float4(biz.x + bhz.x, biz.y + bhz.y, biz.z + bhz.z, biz.w + bhz.w);
            Bn = bin;   // input-side n bias
            Gn = bhn;   // hidden-side n bias
        }

        float h0[4] = {0.f, 0.f, 0.f, 0.f};
        float h1[4] = {0.f, 0.f, 0.f, 0.f};

        #define GATE_PHASE(P, HV, HRDY)                                           \
            do {                                                                  \
                float4 dr = *(const float4*)&gh_sh[P][j];                         \
                float4 dz = *(const float4*)&gh_sh[P][HID + j];                   \
                float4 dn = *(const float4*)&gh_sh[P][2 * HID + j];               \
                float xv = x_sh[P][s];                                            \
                const float* pr = (const float*)&dr;                              \
                const float* pz = (const float*)&dz;                              \
                const float* pn = (const float*)&dn;                              \
                const float* wr = (const float*)&Wr;                              \
                const float* wz = (const float*)&Wz;                              \
                const float* wn = (const float*)&Wn;                              \
                const float* br = (const float*)&Br;                              \
                const float* bz = (const float*)&Bz;                              \
                const float* bn = (const float*)&Bn;                              \
                const float* gn = (const float*)&Gn;                              \
                _Pragma("unroll")                                                 \
                for (int k = 0; k < 4; k++) {                                     \
                    float r = fsig(fmaf(xv, wr[k], br[k]) + pr[k]);               \
                    float z = fsig(fmaf(xv, wz[k], bz[k]) + pz[k]);               \
                    float n = ftanh(fmaf(xv, wn[k], bn[k]) + r * (pn[k] + gn[k]));\
                    HV[k] = n + z * (HV[k] - n);                                  \
                }                                                                 \
                *(float4*)&h_sh[P][j] =                                           \
                    make_float4(HV[0], HV[1], HV[2], HV[3]);                      \
                if (s + 1 < SEQ) BAR_ARRIVE(HRDY);                                \
            } while (0)

        for (int s = 0; s < SEQ; s++) {
            BAR_SYNC(1);                 // gh[0] ready
            GATE_PHASE(0, h0, 3);
            BAR_SYNC(2);                 // gh[1] ready
            GATE_PHASE(1, h1, 4);
        }

        // ---- fused fc1: out[b] = relu(hT) . w_fc + b_fc (gate warp only) ----
        float4 Wf = *(const float4*)(w_fc + j);
        const float* wf = (const float*)&Wf;
        float p0 = 0.f, p1 = 0.f;
        #pragma unroll
        for (int k = 0; k < 4; k++) {
            p0 = fmaf(fmaxf(h0[k], 0.f), wf[k], p0);
            p1 = fmaf(fmaxf(h1[k], 0.f), wf[k], p1);
        }
        #pragma unroll
        for (int off = 16; off; off >>= 1) {
            p0 += __shfl_xor_sync(0xffffffffu, p0, off);
            p1 += __shfl_xor_sync(0xffffffffu, p1, off);
        }
        if ((t & 31) == 0) {
            float bf = b_fc[0];
            out[b0]     = p0 + bf;
            out[b0 + 1] = p1 + bf;
        }
    }
}

extern "C" void kernel_launch(void* const* d_in, const int* in_sizes, int n_in,
                              void* d_out, int out_size) {
    const float* x    = (const float*)d_in[0];
    const float* w_ih = (const float*)d_in[1];
    const float* w_hh = (const float*)d_in[2];
    const float* b_ih = (const float*)d_in[3];
    const float* b_hh = (const float*)d_in[4];
    const float* w_fc = (const float*)d_in[5];
    const float* b_fc = (const float*)d_in[6];
    float* out = (float*)d_out;

    gru_fused_kernel<<<NCTA, NTOT>>>(x, w_ih, w_hh, b_ih, b_hh, w_fc, b_fc, out);
}

// round 6
// speedup vs baseline: 2.1346x; 2.1346x over previous
#include <cuda_runtime.h>

// Problem constants (B=256, S=1024, H=128)
#define SEQ   1024
#define HID   128
#define NTHR  384            // 12 warps, lockstep
#define BPC   2              // batches per CTA
#define NCTA  128            // single wave on 148 SMs

// Packed 2xfp32 FMA (Blackwell f32x2; ptxas won't auto-fuse from C++)
__device__ __forceinline__ unsigned long long ffma2(unsigned long long a,
                                                    unsigned long long b,
                                                    unsigned long long c) {
    unsigned long long d;
    asm("fma.rn.f32x2 %0, %1, %2, %3;" : "=l"(d) : "l"(a), "l"(b), "l"(c));
    return d;
}

__device__ __forceinline__ float2 unpack_f32x2(unsigned long long v) {
    float2 f;
    asm("mov.b64 {%0, %1}, %2;" : "=f"(f.x), "=f"(f.y) : "l"(v));
    return f;
}

// MUFU-only sigmoid / tanh (EX2 + RCP via __expf / __fdividef, rel err ~1e-6)
__device__ __forceinline__ float fsig(float s) {
    float e = __expf(-s);                 // inf for s<-88 -> rcp(inf)=0 -> 0 (ok)
    return __fdividef(1.0f, 1.0f + e);
}
__device__ __forceinline__ float ftanh(float s) {
    s = fminf(fmaxf(s, -10.0f), 10.0f);   // keep exp finite; tanh(±10)=±1 to fp32
    float e = __expf(-2.0f * s);
    return __fdividef(1.0f - e, 1.0f + e);
}

__global__ void __launch_bounds__(NTHR, 1)
gru_fused_kernel(const float* __restrict__ x,     // [B, S]
                 const float* __restrict__ w_ih,  // [3H]
                 const float* __restrict__ w_hh,  // [3H, H]
                 const float* __restrict__ b_ih,  // [3H]
                 const float* __restrict__ b_hh,  // [3H]
                 const float* __restrict__ w_fc,  // [H]
                 const float* __restrict__ b_fc,  // [1]
                 float* __restrict__ out)         // [B]
{
    __shared__ __align__(16) float x_sh[BPC][SEQ];       // 8 KB
    __shared__ __align__(16) float h_sh[BPC][HID];
    __shared__ __align__(16) float gh_sh[BPC][3 * HID];  // raw W_hh.h dots

    const int t  = threadIdx.x;
    const int b0 = blockIdx.x * BPC;

    // Tiling: thread covers rows {r0, r0+1} x cols [64*cg, 64*cg+64)
    const int cg = t & 1;            // column half
    const int r0 = t & ~1;           // even row of the pair (= 2*(t>>1))

    // ---- weights: 2 rows x 64 cols = 64 x f32x2 in registers ----
    unsigned long long w2[64];
    {
        const ulonglong2* wr0 = reinterpret_cast<const ulonglong2*>(w_hh + r0 * HID + cg * 64);
        const ulonglong2* wr1 = reinterpret_cast<const ulonglong2*>(w_hh + (r0 + 1) * HID + cg * 64);
        #pragma unroll
        for (int i = 0; i < 16; i++) {
            ulonglong2 v0 = wr0[i];
            w2[2 * i]      = v0.x;
            w2[2 * i + 1]  = v0.y;
        }
        #pragma unroll
        for (int i = 0; i < 16; i++) {
            ulonglong2 v1 = wr1[i];
            w2[32 + 2 * i]     = v1.x;
            w2[32 + 2 * i + 1] = v1.y;
        }
    }

    // ---- gate-thread constants (used by t<256 only; indices valid for all t) ----
    const int bb = (t >> 7) & 1;     // batch for gate duty
    const int jj = t & (HID - 1);    // hidden unit for gate duty
    const float Ar  = w_ih[jj];
    const float Az  = w_ih[HID + jj];
    const float An  = w_ih[2 * HID + jj];
    const float Cr  = b_ih[jj]           + b_hh[jj];
    const float Cz  = b_ih[HID + jj]     + b_hh[HID + jj];
    const float Cni = b_ih[2 * HID + jj];
    const float Cnh = b_hh[2 * HID + jj];
    float hprev = 0.0f;

    // ---- stage x (both batch rows contiguous), zero h ----
    {
        const float4* xg = reinterpret_cast<const float4*>(x + b0 * SEQ);
        float4* xs = reinterpret_cast<float4*>(&x_sh[0][0]);
        for (int i = t; i < BPC * SEQ / 4; i += NTHR)
            xs[i] = xg[i];
    }
    if (t < BPC * HID)
        (&h_sh[0][0])[t] = 0.0f;
    __syncthreads();

    for (int s = 0; s < SEQ; s++) {
        // ================= matvec (all 384 threads) =================
        {
            const ulonglong2* h0p = reinterpret_cast<const ulonglong2*>(h_sh[0] + cg * 64);
            const ulonglong2* h1p = reinterpret_cast<const ulonglong2*>(h_sh[1] + cg * 64);
            unsigned long long a00 = 0ull, a10 = 0ull;   // (row0,b0) (row1,b0)
            unsigned long long a01 = 0ull, a11 = 0ull;   // (row0,b1) (row1,b1)
            #pragma unroll
            for (int i = 0; i < 16; i++) {
                ulonglong2 v0 = h0p[i];       // batch0: 4 h values
                ulonglong2 v1 = h1p[i];       // batch1
                a00 = ffma2(w2[2 * i],          v0.x, a00);
                a00 = ffma2(w2[2 * i + 1],      v0.y, a00);
                a10 = ffma2(w2[32 + 2 * i],     v0.x, a10);
                a10 = ffma2(w2[32 + 2 * i + 1], v0.y, a10);
                a01 = ffma2(w2[2 * i],          v1.x, a01);
                a01 = ffma2(w2[2 * i + 1],      v1.y, a01);
                a11 = ffma2(w2[32 + 2 * i],     v1.x, a11);
                a11 = ffma2(w2[32 + 2 * i + 1], v1.y, a11);
            }
            float2 f;
            f = unpack_f32x2(a00); float d00 = f.x + f.y;
            f = unpack_f32x2(a10); float d10 = f.x + f.y;
            f = unpack_f32x2(a01); float d01 = f.x + f.y;
            f = unpack_f32x2(a11); float d11 = f.x + f.y;
            // combine column halves (lane pair t, t^1)
            d00 += __shfl_xor_sync(0xffffffffu, d00, 1);
            d10 += __shfl_xor_sync(0xffffffffu, d10, 1);
            d01 += __shfl_xor_sync(0xffffffffu, d01, 1);
            d11 += __shfl_xor_sync(0xffffffffu, d11, 1);
            // split store duty: even lane -> batch0 pair, odd lane -> batch1 pair
            if (cg == 0)
                *reinterpret_cast<float2*>(&gh_sh[0][r0]) = make_float2(d00, d10);
            else
                *reinterpret_cast<float2*>(&gh_sh[1][r0]) = make_float2(d01, d11);
        }
        __syncthreads();

        // ================= gates (threads 0..255, 1 unit each) =================
        if (t < BPC * HID) {
            float xv = x_sh[bb][s];
            float dr = gh_sh[bb][jj];
            float dz = gh_sh[bb][HID + jj];
            float dn = gh_sh[bb][2 * HID + jj];
            float r  = fsig(fmaf(xv, Ar, Cr) + dr);
            float z  = fsig(fmaf(xv, Az, Cz) + dz);
            float n  = ftanh(fmaf(xv, An, Cni) + r * (dn + Cnh));
            hprev = n + z * (hprev - n);
            h_sh[bb][jj] = hprev;
        }
        __syncthreads();
    }

    // ---- fused fc1: out[b] = relu(hT) . w_fc + b_fc ----
    if (t < BPC * HID)
        (&gh_sh[0][0])[t] = fmaxf(hprev, 0.0f) * w_fc[jj];
    __syncthreads();
    if (t < BPC) {
        float acc = b_fc[0];
        #pragma unroll 8
        for (int k = 0; k < HID; k++)
            acc += (&gh_sh[0][0])[t * HID + k];
        out[b0 + t] = acc;
    }
}

extern "C" void kernel_launch(void* const* d_in, const int* in_sizes, int n_in,
                              void* d_out, int out_size) {
    const float* x    = (const float*)d_in[0];
    const float* w_ih = (const float*)d_in[1];
    const float* w_hh = (const float*)d_in[2];
    const float* b_ih = (const float*)d_in[3];
    const float* b_hh = (const float*)d_in[4];
    const float* w_fc = (const float*)d_in[5];
    const float* b_fc = (const float*)d_in[6];
    float* out = (float*)d_out;

    gru_fused_kernel<<<NCTA, NTHR>>>(x, w_ih, w_hh, b_ih, b_hh, w_fc, b_fc, out);
}

// round 7
// speedup vs baseline: 2.1471x; 1.0059x over previous
#include <cuda_runtime.h>

// Problem constants (B=256, S=1024, H=128)
#define SEQ   1024
#define HID   128
#define NTHR  384            // 12 warps: warps 0-7 = r/z rows, warps 8-11 = n rows
#define BPC   2              // batches per CTA
#define NCTA  128            // single wave on 148 SMs

// Packed 2xfp32 FMA (Blackwell f32x2; ptxas won't auto-fuse from C++)
__device__ __forceinline__ unsigned long long ffma2(unsigned long long a,
                                                    unsigned long long b,
                                                    unsigned long long c) {
    unsigned long long d;
    asm("fma.rn.f32x2 %0, %1, %2, %3;" : "=l"(d) : "l"(a), "l"(b), "l"(c));
    return d;
}

__device__ __forceinline__ float2 unpack_f32x2(unsigned long long v) {
    float2 f;
    asm("mov.b64 {%0, %1}, %2;" : "=f"(f.x), "=f"(f.y) : "l"(v));
    return f;
}

// MUFU-only sigmoid / tanh (EX2 + RCP, rel err ~1e-6)
__device__ __forceinline__ float fsig(float s) {
    float e = __expf(-s);                 // inf for very negative -> rcp -> 0 (ok)
    return __fdividef(1.0f, 1.0f + e);
}
__device__ __forceinline__ float ftanh(float s) {
    s = fminf(fmaxf(s, -10.0f), 10.0f);   // keep exp finite; tanh(+-10)=+-1 in fp32
    float e = __expf(-2.0f * s);
    return __fdividef(1.0f - e, 1.0f + e);
}

__global__ void __launch_bounds__(NTHR, 1)
gru_fused_kernel(const float* __restrict__ x,     // [B, S]
                 const float* __restrict__ w_ih,  // [3H]
                 const float* __restrict__ w_hh,  // [3H, H]
                 const float* __restrict__ b_ih,  // [3H]
                 const float* __restrict__ b_hh,  // [3H]
                 const float* __restrict__ w_fc,  // [H]
                 const float* __restrict__ b_fc,  // [1]
                 float* __restrict__ out)         // [B]
{
    __shared__ __align__(16) float x_sh[BPC][SEQ];       // 8 KB
    __shared__ __align__(16) float h_sh[BPC][HID];
    __shared__ __align__(16) float rz_sh[BPC][2 * HID];  // ACTIVATED r,z (sigmoided)

    const int t  = threadIdx.x;
    const int b0 = blockIdx.x * BPC;

    // Tiling: thread covers rows {r0, r0+1} x cols [64*cg, 64*cg+64)
    const int cg = t & 1;            // column half
    const int r0 = t & ~1;           // even row of the pair
    const int R  = r0 + cg;          // the row this lane FINALIZES after shfl

    // ---- weights: 2 rows x 64 cols = 64 x f32x2 in registers ----
    unsigned long long w2[64];
    {
        const ulonglong2* wr0 = reinterpret_cast<const ulonglong2*>(w_hh + r0 * HID + cg * 64);
        const ulonglong2* wr1 = reinterpret_cast<const ulonglong2*>(w_hh + (r0 + 1) * HID + cg * 64);
        #pragma unroll
        for (int i = 0; i < 16; i++) {
            ulonglong2 v0 = wr0[i];
            w2[2 * i]     = v0.x;
            w2[2 * i + 1] = v0.y;
        }
        #pragma unroll
        for (int i = 0; i < 16; i++) {
            ulonglong2 v1 = wr1[i];
            w2[32 + 2 * i]     = v1.x;
            w2[32 + 2 * i + 1] = v1.y;
        }
    }

    // ---- per-lane gate constants for finalized row R ----
    const float A_R  = w_ih[R];                    // input weight of row R
    const float Bi_R = b_ih[R];
    const float Bh_R = b_hh[R];
    const float C_R  = Bi_R + Bh_R;                // combined bias (r/z use)
    const int   u    = R - 2 * HID;                // hidden unit (n rows only)
    const bool  is_n = (t >= 2 * HID);             // warps 8-11 (uniform per warp)
    float h0 = 0.0f, h1 = 0.0f;                    // h_prev for unit u (n lanes)

    // ---- stage x (both batch rows contiguous), zero h ----
    {
        const float4* xg = reinterpret_cast<const float4*>(x + b0 * SEQ);
        float4* xs = reinterpret_cast<float4*>(&x_sh[0][0]);
        for (int i = t; i < BPC * SEQ / 4; i += NTHR)
            xs[i] = xg[i];
    }
    if (t < BPC * HID)
        (&h_sh[0][0])[t] = 0.0f;
    __syncthreads();

    for (int s = 0; s < SEQ; s++) {
        // ================= matvec (all 384 threads) =================
        const ulonglong2* h0p = reinterpret_cast<const ulonglong2*>(h_sh[0] + cg * 64);
        const ulonglong2* h1p = reinterpret_cast<const ulonglong2*>(h_sh[1] + cg * 64);
        unsigned long long a00 = 0ull, a10 = 0ull;   // (row0,b0) (row1,b0)
        unsigned long long a01 = 0ull, a11 = 0ull;   // (row0,b1) (row1,b1)
        #pragma unroll
        for (int i = 0; i < 16; i++) {
            ulonglong2 v0 = h0p[i];       // batch0: 4 h values
            ulonglong2 v1 = h1p[i];       // batch1
            a00 = ffma2(w2[2 * i],          v0.x, a00);
            a00 = ffma2(w2[2 * i + 1],      v0.y, a00);
            a10 = ffma2(w2[32 + 2 * i],     v0.x, a10);
            a10 = ffma2(w2[32 + 2 * i + 1], v0.y, a10);
            a01 = ffma2(w2[2 * i],          v1.x, a01);
            a01 = ffma2(w2[2 * i + 1],      v1.y, a01);
            a11 = ffma2(w2[32 + 2 * i],     v1.x, a11);
            a11 = ffma2(w2[32 + 2 * i + 1], v1.y, a11);
        }
        float xv0 = x_sh[0][s];           // overlap with shfl below
        float xv1 = x_sh[1][s];
        float2 f;
        f = unpack_f32x2(a00); float s00 = f.x + f.y;  // row r0,  b0, my half
        f = unpack_f32x2(a10); float s10 = f.x + f.y;  // row r0+1,b0
        f = unpack_f32x2(a01); float s01 = f.x + f.y;  // row r0,  b1
        f = unpack_f32x2(a11); float s11 = f.x + f.y;  // row r0+1,b1

        // 2-shfl exchange: even lane finalizes row r0, odd lane row r0+1
        float send0 = cg ? s00 : s10;     // give partner the row IT finalizes
        float send1 = cg ? s01 : s11;
        float recv0 = __shfl_xor_sync(0xffffffffu, send0, 1);
        float recv1 = __shfl_xor_sync(0xffffffffu, send1, 1);
        float d0 = (cg ? s10 : s00) + recv0;   // full dot, row R, batch 0
        float d1 = (cg ? s11 : s01) + recv1;   // full dot, row R, batch 1

        if (!is_n) {
            // r/z rows: apply sigmoid NOW (off the serial path), store activated
            float g0 = fsig(fmaf(xv0, A_R, C_R) + d0);
            float g1 = fsig(fmaf(xv1, A_R, C_R) + d1);
            rz_sh[0][R] = g0;
            rz_sh[1][R] = g1;
        }
        __syncthreads();   // sigma(r), sigma(z) visible

        if (is_n) {
            // n rows: dn held in registers (d0,d1); only 4 LDS for r,z
            float r0g = rz_sh[0][u];
            float z0g = rz_sh[0][HID + u];
            float r1g = rz_sh[1][u];
            float z1g = rz_sh[1][HID + u];
            float n0 = ftanh(fmaf(xv0, A_R, Bi_R) + r0g * (d0 + Bh_R));
            float n1 = ftanh(fmaf(xv1, A_R, Bi_R) + r1g * (d1 + Bh_R));
            h0 = n0 + z0g * (h0 - n0);
            h1 = n1 + z1g * (h1 - n1);
            h_sh[0][u] = h0;
            h_sh[1][u] = h1;
        }
        __syncthreads();   // new h visible
    }

    // ---- fused fc1: out[b] = relu(hT) . w_fc + b_fc ----
    if (is_n) {
        float wf = w_fc[u];
        rz_sh[0][u] = fmaxf(h0, 0.0f) * wf;
        rz_sh[1][u] = fmaxf(h1, 0.0f) * wf;
    }
    __syncthreads();
    if (t < BPC) {
        float acc = b_fc[0];
        #pragma unroll 8
        for (int k = 0; k < HID; k++)
            acc += rz_sh[t][k];
        out[b0 + t] = acc;
    }
}

extern "C" void kernel_launch(void* const* d_in, const int* in_sizes, int n_in,
                              void* d_out, int out_size) {
    const float* x    = (const float*)d_in[0];
    const float* w_ih = (const float*)d_in[1];
    const float* w_hh = (const float*)d_in[2];
    const float* b_ih = (const float*)d_in[3];
    const float* b_hh = (const float*)d_in[4];
    const float* w_fc = (const float*)d_in[5];
    const float* b_fc = (const float*)d_in[6];
    float* out = (float*)d_out;

    gru_fused_kernel<<<NCTA, NTHR>>>(x, w_ih, w_hh, b_ih, b_hh, w_fc, b_fc, out);
}

// round 8
// speedup vs baseline: 3.0988x; 1.4432x over previous
#include <cuda_runtime.h>

// Problem constants (B=256, S=1024, H=128)
#define SEQ   1024
#define HID   128
#define NTHR  256            // 8 warps; lane pair = col halves of one unit
#define BPC   2              // batches per CTA
#define NCTA  128            // single wave on 148 SMs

#define XPAD  1040           // x row stride (bank offset 16 between rows)
#define HPAD  144            // h row stride (bank offset 16 between batches)

// Packed 2xfp32 FMA (Blackwell f32x2; ptxas won't auto-fuse from C++)
__device__ __forceinline__ unsigned long long ffma2(unsigned long long a,
                                                    unsigned long long b,
                                                    unsigned long long c) {
    unsigned long long d;
    asm("fma.rn.f32x2 %0, %1, %2, %3;" : "=l"(d) : "l"(a), "l"(b), "l"(c));
    return d;
}

__device__ __forceinline__ float2 unpack_f32x2(unsigned long long v) {
    float2 f;
    asm("mov.b64 {%0, %1}, %2;" : "=f"(f.x), "=f"(f.y) : "l"(v));
    return f;
}

// MUFU-only sigmoid / tanh (EX2 + RCP, rel err ~1e-6)
__device__ __forceinline__ float fsig(float s) {
    float e = __expf(-s);
    return __fdividef(1.0f, 1.0f + e);
}
__device__ __forceinline__ float ftanh(float s) {
    s = fminf(fmaxf(s, -10.0f), 10.0f);
    float e = __expf(-2.0f * s);
    return __fdividef(1.0f - e, 1.0f + e);
}

__global__ void __launch_bounds__(NTHR, 1)
gru_fused_kernel(const float* __restrict__ x,     // [B, S]
                 const float* __restrict__ w_ih,  // [3H]
                 const float* __restrict__ w_hh,  // [3H, H]
                 const float* __restrict__ b_ih,  // [3H]
                 const float* __restrict__ b_hh,  // [3H]
                 const float* __restrict__ w_fc,  // [H]
                 const float* __restrict__ b_fc,  // [1]
                 float* __restrict__ out)         // [B]
{
    // padded layouts: conflict-free for the even/odd half-lane access pattern
    __shared__ __align__(16) float x_sh[BPC][XPAD];          // 8.1 KB
    __shared__ __align__(16) float h_sh[2][BPC][HPAD];       // double-buffered h
    __shared__ __align__(16) float red_sh[BPC * HID];        // fc scratch

    const int t    = threadIdx.x;
    const int b0   = blockIdx.x * BPC;
    const int u    = t >> 1;            // hidden unit owned by this lane pair
    const int half = t & 1;             // col half AND batch this lane finalizes

    // ---- weights: rows {u, u+128, u+256} x cols [half*64, half*64+64) ----
    // 3 x 32 f32x2 = 192 registers
    unsigned long long wr_[32], wz_[32], wn_[32];
    {
        const ulonglong2* pr = reinterpret_cast<const ulonglong2*>(w_hh + u * HID + half * 64);
        const ulonglong2* pz = reinterpret_cast<const ulonglong2*>(w_hh + (u + HID) * HID + half * 64);
        const ulonglong2* pn = reinterpret_cast<const ulonglong2*>(w_hh + (u + 2 * HID) * HID + half * 64);
        #pragma unroll
        for (int i = 0; i < 16; i++) { ulonglong2 v = pr[i]; wr_[2*i] = v.x; wr_[2*i+1] = v.y; }
        #pragma unroll
        for (int i = 0; i < 16; i++) { ulonglong2 v = pz[i]; wz_[2*i] = v.x; wz_[2*i+1] = v.y; }
        #pragma unroll
        for (int i = 0; i < 16; i++) { ulonglong2 v = pn[i]; wn_[2*i] = v.x; wn_[2*i+1] = v.y; }
    }

    // ---- per-lane gate constants (unit u) ----
    const float Ar  = w_ih[u];
    const float Az  = w_ih[HID + u];
    const float An  = w_ih[2 * HID + u];
    const float Cr  = b_ih[u]         + b_hh[u];
    const float Cz  = b_ih[HID + u]   + b_hh[HID + u];
    const float Cni = b_ih[2 * HID + u];
    const float Cnh = b_hh[2 * HID + u];
    float hprev = 0.0f;                 // h[u] for batch `half`

    // ---- stage x, zero h buffer 0 ----
    for (int i = t; i < SEQ; i += NTHR) {
        x_sh[0][i] = x[b0 * SEQ + i];
        x_sh[1][i] = x[(b0 + 1) * SEQ + i];
    }
    if (t < BPC * HID)
        h_sh[0][t >> 7][(t & 127) + (((t & 127) & 64) >> 4)] = 0.0f;  // pos skew +4 at 64
    __syncthreads();

    const int hwr = u + ((u & 64) >> 4);     // skewed write position for unit u

    for (int s = 0; s < SEQ; s++) {
        const int rb = s & 1;                // read buffer
        const float* hb0 = h_sh[rb][0] + half * 68;   // skewed half base
        const float* hb1 = h_sh[rb][1] + half * 68;
        const ulonglong2* hp0 = reinterpret_cast<const ulonglong2*>(hb0);
        const ulonglong2* hp1 = reinterpret_cast<const ulonglong2*>(hb1);

        // 6 accumulator chains: (r,z,n) x (b0,b1)
        unsigned long long ar0 = 0ull, az0 = 0ull, an0 = 0ull;
        unsigned long long ar1 = 0ull, az1 = 0ull, an1 = 0ull;
        #pragma unroll
        for (int i = 0; i < 16; i++) {
            ulonglong2 v0 = hp0[i];          // 4 h values, batch 0 (conflict-free)
            ulonglong2 v1 = hp1[i];          // batch 1
            ar0 = ffma2(wr_[2*i],   v0.x, ar0);
            az0 = ffma2(wz_[2*i],   v0.x, az0);
            an0 = ffma2(wn_[2*i],   v0.x, an0);
            ar1 = ffma2(wr_[2*i],   v1.x, ar1);
            az1 = ffma2(wz_[2*i],   v1.x, az1);
            an1 = ffma2(wn_[2*i],   v1.x, an1);
            ar0 = ffma2(wr_[2*i+1], v0.y, ar0);
            az0 = ffma2(wz_[2*i+1], v0.y, az0);
            an0 = ffma2(wn_[2*i+1], v0.y, an0);
            ar1 = ffma2(wr_[2*i+1], v1.y, ar1);
            az1 = ffma2(wz_[2*i+1], v1.y, az1);
            an1 = ffma2(wn_[2*i+1], v1.y, an1);
        }
        float2 f;
        f = unpack_f32x2(ar0); float fr0 = f.x + f.y;
        f = unpack_f32x2(az0); float fz0 = f.x + f.y;
        f = unpack_f32x2(an0); float fn0 = f.x + f.y;
        f = unpack_f32x2(ar1); float fr1 = f.x + f.y;
        f = unpack_f32x2(az1); float fz1 = f.x + f.y;
        f = unpack_f32x2(an1); float fn1 = f.x + f.y;

        // 3-shfl exchange: lane keeps batch==half, sends the other batch
        float sr = half ? fr0 : fr1;
        float sz = half ? fz0 : fz1;
        float sn = half ? fn0 : fn1;
        float rr = __shfl_xor_sync(0xffffffffu, sr, 1);
        float rz = __shfl_xor_sync(0xffffffffu, sz, 1);
        float rn = __shfl_xor_sync(0xffffffffu, sn, 1);
        float d_r = (half ? fr1 : fr0) + rr;
        float d_z = (half ? fz1 : fz0) + rz;
        float d_n = (half ? fn1 : fn0) + rn;

        // ---- gates, fully local (batch = half) ----
        float xv = x_sh[half][s];
        float r  = fsig(fmaf(xv, Ar, Cr) + d_r);
        float z  = fsig(fmaf(xv, Az, Cz) + d_z);
        float n  = ftanh(fmaf(xv, An, Cni) + r * (d_n + Cnh));
        hprev = n + z * (hprev - n);
        h_sh[rb ^ 1][half][hwr] = hprev;     // write NEXT buffer
        __syncthreads();                     // single barrier per step
    }

    // ---- fused fc1: out[b] = relu(hT) . w_fc + b_fc ----
    red_sh[half * HID + u] = fmaxf(hprev, 0.0f) * w_fc[u];
    __syncthreads();
    if (t < BPC) {
        float acc = b_fc[0];
        #pragma unroll 8
        for (int k = 0; k < HID; k++)
            acc += red_sh[t * HID + k];
        out[b0 + t] = acc;
    }
}

extern "C" void kernel_launch(void* const* d_in, const int* in_sizes, int n_in,
                              void* d_out, int out_size) {
    const float* x    = (const float*)d_in[0];
    const float* w_ih = (const float*)d_in[1];
    const float* w_hh = (const float*)d_in[2];
    const float* b_ih = (const float*)d_in[3];
    const float* b_hh = (const float*)d_in[4];
    const float* w_fc = (const float*)d_in[5];
    const float* b_fc = (const float*)d_in[6];
    float* out = (float*)d_out;

    gru_fused_kernel<<<NCTA, NTHR>>>(x, w_ih, w_hh, b_ih, b_hh, w_fc, b_fc, out);
}

// round 9
// speedup vs baseline: 3.3771x; 1.0898x over previous
#include <cuda_runtime.h>

// Problem constants (B=256, S=1024, H=128)
#define SEQ   1024
#define HID   128
#define NTHR  256            // 8 warps; lane pair = col halves of one unit
#define BPC   2              // batches per CTA
#define NCTA  128            // single wave on 148 SMs

#define XPAD  1040           // x row stride (bank offset 16 between rows)
#define HPAD  144            // h row stride (bank offset 16 between batches)

// Packed 2xfp32 FMA (Blackwell f32x2; ptxas won't auto-fuse from C++)
__device__ __forceinline__ unsigned long long ffma2(unsigned long long a,
                                                    unsigned long long b,
                                                    unsigned long long c) {
    unsigned long long d;
    asm("fma.rn.f32x2 %0, %1, %2, %3;" : "=l"(d) : "l"(a), "l"(b), "l"(c));
    return d;
}

__device__ __forceinline__ float2 unpack_f32x2(unsigned long long v) {
    float2 f;
    asm("mov.b64 {%0, %1}, %2;" : "=f"(f.x), "=f"(f.y) : "l"(v));
    return f;
}

// Single-MUFU transcendentals (sm_75+ tanh unit)
__device__ __forceinline__ float tanha(float x) {
    float y;
    asm("tanh.approx.f32 %0, %1;" : "=f"(y) : "f"(x));
    return y;
}
__device__ __forceinline__ float fsig(float s) {      // sigma(s) = 0.5*tanh(s/2)+0.5
    return fmaf(tanha(s * 0.5f), 0.5f, 0.5f);
}

__global__ void __launch_bounds__(NTHR, 1)
gru_fused_kernel(const float* __restrict__ x,     // [B, S]
                 const float* __restrict__ w_ih,  // [3H]
                 const float* __restrict__ w_hh,  // [3H, H]
                 const float* __restrict__ b_ih,  // [3H]
                 const float* __restrict__ b_hh,  // [3H]
                 const float* __restrict__ w_fc,  // [H]
                 const float* __restrict__ b_fc,  // [1]
                 float* __restrict__ out)         // [B]
{
    __shared__ __align__(16) float x_sh[BPC][XPAD];
    __shared__ __align__(16) float h_sh[2][BPC][HPAD];   // double-buffered h
    __shared__ __align__(16) float red_sh[BPC * HID];

    const int t    = threadIdx.x;
    const int b0   = blockIdx.x * BPC;
    const int u    = t >> 1;            // hidden unit owned by this lane pair
    const int half = t & 1;             // col half AND batch this lane finalizes

    // ---- weights: rows {u, u+128, u+256} x cols [half*64, half*64+64) ----
    unsigned long long wr_[32], wz_[32], wn_[32];
    {
        const ulonglong2* pr = reinterpret_cast<const ulonglong2*>(w_hh + u * HID + half * 64);
        const ulonglong2* pz = reinterpret_cast<const ulonglong2*>(w_hh + (u + HID) * HID + half * 64);
        const ulonglong2* pn = reinterpret_cast<const ulonglong2*>(w_hh + (u + 2 * HID) * HID + half * 64);
        #pragma unroll
        for (int i = 0; i < 16; i++) { ulonglong2 v = pr[i]; wr_[2*i] = v.x; wr_[2*i+1] = v.y; }
        #pragma unroll
        for (int i = 0; i < 16; i++) { ulonglong2 v = pz[i]; wz_[2*i] = v.x; wz_[2*i+1] = v.y; }
        #pragma unroll
        for (int i = 0; i < 16; i++) { ulonglong2 v = pn[i]; wn_[2*i] = v.x; wn_[2*i+1] = v.y; }
    }

    // ---- per-lane gate constants (unit u) ----
    const float Ar  = w_ih[u];
    const float Az  = w_ih[HID + u];
    const float An  = w_ih[2 * HID + u];
    const float Cr  = b_ih[u]         + b_hh[u];
    const float Cz  = b_ih[HID + u]   + b_hh[HID + u];
    const float Cni = b_ih[2 * HID + u];
    const float Cnh = b_hh[2 * HID + u];
    float hprev = 0.0f;                 // h[u] for batch `half`

    // ---- stage x, zero h buffer 0 ----
    for (int i = t; i < SEQ; i += NTHR) {
        x_sh[0][i] = x[b0 * SEQ + i];
        x_sh[1][i] = x[(b0 + 1) * SEQ + i];
    }
    if (t < BPC * HID)
        h_sh[0][t >> 7][(t & 127) + (((t & 127) & 64) >> 4)] = 0.0f;
    __syncthreads();

    const int hwr = u + ((u & 64) >> 4);     // skewed write position for unit u

    // One GRU step reading h buffer RB, writing buffer RB^1
    #define STEP(RB, SIDX)                                                       \
    do {                                                                         \
        /* gi pre-activations: off the serial tail, fills barrier window */      \
        float xv  = x_sh[half][SIDX];                                            \
        float gir = fmaf(xv, Ar, Cr);                                            \
        float giz = fmaf(xv, Az, Cz);                                            \
        float gin = fmaf(xv, An, Cni);                                           \
        const ulonglong2* hp0 =                                                  \
            reinterpret_cast<const ulonglong2*>(h_sh[RB][0] + half * 68);        \
        const ulonglong2* hp1 =                                                  \
            reinterpret_cast<const ulonglong2*>(h_sh[RB][1] + half * 68);        \
        unsigned long long ar0 = 0ull, az0 = 0ull, an0 = 0ull;                   \
        unsigned long long ar1 = 0ull, az1 = 0ull, an1 = 0ull;                   \
        _Pragma("unroll")                                                        \
        for (int i = 0; i < 16; i++) {                                           \
            ulonglong2 v0 = hp0[i];                                              \
            ulonglong2 v1 = hp1[i];                                              \
            ar0 = ffma2(wr_[2*i],   v0.x, ar0);                                  \
            az0 = ffma2(wz_[2*i],   v0.x, az0);                                  \
            an0 = ffma2(wn_[2*i],   v0.x, an0);                                  \
            ar1 = ffma2(wr_[2*i],   v1.x, ar1);                                  \
            az1 = ffma2(wz_[2*i],   v1.x, az1);                                  \
            an1 = ffma2(wn_[2*i],   v1.x, an1);                                  \
            ar0 = ffma2(wr_[2*i+1], v0.y, ar0);                                  \
            az0 = ffma2(wz_[2*i+1], v0.y, az0);                                  \
            an0 = ffma2(wn_[2*i+1], v0.y, an0);                                  \
            ar1 = ffma2(wr_[2*i+1], v1.y, ar1);                                  \
            az1 = ffma2(wz_[2*i+1], v1.y, az1);                                  \
            an1 = ffma2(wn_[2*i+1], v1.y, an1);                                  \
        }                                                                        \
        float2 f;                                                                \
        f = unpack_f32x2(ar0); float fr0 = f.x + f.y;                            \
        f = unpack_f32x2(az0); float fz0 = f.x + f.y;                            \
        f = unpack_f32x2(an0); float fn0 = f.x + f.y;                            \
        f = unpack_f32x2(ar1); float fr1 = f.x + f.y;                            \
        f = unpack_f32x2(az1); float fz1 = f.x + f.y;                            \
        f = unpack_f32x2(an1); float fn1 = f.x + f.y;                            \
        /* 3-shfl exchange: keep batch==half, send the other */                  \
        float sr = half ? fr0 : fr1;                                             \
        float sz = half ? fz0 : fz1;                                             \
        float sn = half ? fn0 : fn1;                                             \
        float rr = __shfl_xor_sync(0xffffffffu, sr, 1);                          \
        float rz = __shfl_xor_sync(0xffffffffu, sz, 1);                          \
        float rn = __shfl_xor_sync(0xffffffffu, sn, 1);                          \
        float d_r = (half ? fr1 : fr0) + rr;                                     \
        float d_z = (half ? fz1 : fz0) + rz;                                     \
        float d_n = (half ? fn1 : fn0) + rn;                                     \
        /* gates, single-MUFU each */                                            \
        float r  = fsig(gir + d_r);                                              \
        float z  = fsig(giz + d_z);                                              \
        float n  = tanha(gin + r * (d_n + Cnh));                                 \
        hprev = n + z * (hprev - n);                                             \
        h_sh[(RB) ^ 1][half][hwr] = hprev;                                       \
        __syncthreads();                                                         \
    } while (0)

    for (int s = 0; s < SEQ; s += 2) {
        STEP(0, s);
        STEP(1, s + 1);
    }
    #undef STEP

    // ---- fused fc1: out[b] = relu(hT) . w_fc + b_fc ----
    red_sh[half * HID + u] = fmaxf(hprev, 0.0f) * w_fc[u];
    __syncthreads();
    if (t < BPC) {
        float acc = b_fc[0];
        #pragma unroll 8
        for (int k = 0; k < HID; k++)
            acc += red_sh[t * HID + k];
        out[b0 + t] = acc;
    }
}

extern "C" void kernel_launch(void* const* d_in, const int* in_sizes, int n_in,
                              void* d_out, int out_size) {
    const float* x    = (const float*)d_in[0];
    const float* w_ih = (const float*)d_in[1];
    const float* w_hh = (const float*)d_in[2];
    const float* b_ih = (const float*)d_in[3];
    const float* b_hh = (const float*)d_in[4];
    const float* w_fc = (const float*)d_in[5];
    const float* b_fc = (const float*)d_in[6];
    float* out = (float*)d_out;

    gru_fused_kernel<<<NCTA, NTHR>>>(x, w_ih, w_hh, b_ih, b_hh, w_fc, b_fc, out);
}

// round 10
// speedup vs baseline: 3.7451x; 1.1090x over previous
#include <cuda_runtime.h>
#include <cuda_bf16.h>

// Problem constants (B=256, S=1024, H=128)
#define SEQ   1024
#define HID   128
#define NTHR  256            // 8 warps; lane pair = col halves of one unit
#define BPC   2              // batches per CTA
#define NCTA  128            // single wave on 148 SMs

#define XPAD  1040           // x row stride in floats (bank offset between rows)
#define HROW  144            // bf16 elems per (buffer,batch) row: 64 + 8 pad + 64 + 8

// 16-byte vector of 4 bf16x2 (8 bf16 values)
struct __align__(16) bf16x8 { __nv_bfloat162 v[4]; };

// Single-MUFU transcendentals (sm_75+ tanh unit)
__device__ __forceinline__ float tanha(float x) {
    float y;
    asm("tanh.approx.f32 %0, %1;" : "=f"(y) : "f"(x));
    return y;
}
__device__ __forceinline__ float fsig(float s) {      // sigma(s) = 0.5*tanh(s/2)+0.5
    return fmaf(tanha(s * 0.5f), 0.5f, 0.5f);
}

__global__ void __launch_bounds__(NTHR, 1)
gru_fused_kernel(const float* __restrict__ x,     // [B, S]
                 const float* __restrict__ w_ih,  // [3H]
                 const float* __restrict__ w_hh,  // [3H, H]
                 const float* __restrict__ b_ih,  // [3H]
                 const float* __restrict__ b_hh,  // [3H]
                 const float* __restrict__ w_fc,  // [H]
                 const float* __restrict__ b_fc,  // [1]
                 float* __restrict__ out)         // [B]
{
    __shared__ __align__(16) float x_sh[BPC][XPAD];
    __shared__ __align__(16) __nv_bfloat16 h_sh[2][BPC][HROW];  // double-buffered bf16 h
    __shared__ __align__(16) float red_sh[BPC * HID];

    const int t    = threadIdx.x;
    const int b0   = blockIdx.x * BPC;
    const int u    = t >> 1;            // hidden unit owned by this lane pair
    const int half = t & 1;             // col half AND batch this lane finalizes

    // ---- weights: rows {u, u+128, u+256} x cols [half*64,+64), bf16x2 packed ----
    // 3 x 32 x 32-bit = 96 registers
    __nv_bfloat162 wr_[32], wz_[32], wn_[32];
    {
        const float4* pr = reinterpret_cast<const float4*>(w_hh + u * HID + half * 64);
        const float4* pz = reinterpret_cast<const float4*>(w_hh + (u + HID) * HID + half * 64);
        const float4* pn = reinterpret_cast<const float4*>(w_hh + (u + 2 * HID) * HID + half * 64);
        #pragma unroll
        for (int i = 0; i < 16; i++) {
            float4 a = pr[i];
            wr_[2*i]   = __floats2bfloat162_rn(a.x, a.y);
            wr_[2*i+1] = __floats2bfloat162_rn(a.z, a.w);
        }
        #pragma unroll
        for (int i = 0; i < 16; i++) {
            float4 a = pz[i];
            wz_[2*i]   = __floats2bfloat162_rn(a.x, a.y);
            wz_[2*i+1] = __floats2bfloat162_rn(a.z, a.w);
        }
        #pragma unroll
        for (int i = 0; i < 16; i++) {
            float4 a = pn[i];
            wn_[2*i]   = __floats2bfloat162_rn(a.x, a.y);
            wn_[2*i+1] = __floats2bfloat162_rn(a.z, a.w);
        }
    }

    // ---- per-lane gate constants (unit u), all fp32 ----
    const float Ar  = w_ih[u];
    const float Az  = w_ih[HID + u];
    const float An  = w_ih[2 * HID + u];
    const float Cr  = b_ih[u]         + b_hh[u];
    const float Cz  = b_ih[HID + u]   + b_hh[HID + u];
    const float Cni = b_ih[2 * HID + u];
    const float Cnh = b_hh[2 * HID + u];
    float hprev = 0.0f;                 // fp32 h[u] for batch `half`

    // ---- stage x, zero both h buffers ----
    for (int i = t; i < SEQ; i += NTHR) {
        x_sh[0][i] = x[b0 * SEQ + i];
        x_sh[1][i] = x[(b0 + 1) * SEQ + i];
    }
    for (int i = t; i < 2 * BPC * HROW; i += NTHR)
        (&h_sh[0][0][0])[i] = __float2bfloat16(0.0f);
    __syncthreads();

    // skewed write position: +8 bf16 (16B) offset for upper half -> bank shift
    const int hwr = u + ((u & 64) >> 3);

    // One GRU step reading h buffer RB, writing buffer RB^1
    #define STEP(RB, SIDX)                                                       \
    do {                                                                         \
        float xv  = x_sh[half][SIDX];                                            \
        float gir = fmaf(xv, Ar, Cr);                                            \
        float giz = fmaf(xv, Az, Cz);                                            \
        float gin = fmaf(xv, An, Cni);                                           \
        const bf16x8* hb0 =                                                      \
            reinterpret_cast<const bf16x8*>(&h_sh[RB][0][half * 72]);            \
        const bf16x8* hb1 =                                                      \
            reinterpret_cast<const bf16x8*>(&h_sh[RB][1][half * 72]);            \
        __nv_bfloat162 A0[4], A1[4], A2[4], A3[4], A4[4], A5[4];                 \
        _Pragma("unroll")                                                        \
        for (int j = 0; j < 4; j++) {                                            \
            __nv_bfloat162 zz = __float2bfloat162_rn(0.0f);                      \
            A0[j] = zz; A1[j] = zz; A2[j] = zz;                                  \
            A3[j] = zz; A4[j] = zz; A5[j] = zz;                                  \
        }                                                                        \
        _Pragma("unroll")                                                        \
        for (int i = 0; i < 8; i++) {                                            \
            bf16x8 v0 = hb0[i];                                                  \
            bf16x8 v1 = hb1[i];                                                  \
            _Pragma("unroll")                                                    \
            for (int j = 0; j < 4; j++) {                                        \
                A0[j] = __hfma2(wr_[4*i+j], v0.v[j], A0[j]);                     \
                A1[j] = __hfma2(wz_[4*i+j], v0.v[j], A1[j]);                     \
                A2[j] = __hfma2(wn_[4*i+j], v0.v[j], A2[j]);                     \
                A3[j] = __hfma2(wr_[4*i+j], v1.v[j], A3[j]);                     \
                A4[j] = __hfma2(wz_[4*i+j], v1.v[j], A4[j]);                     \
                A5[j] = __hfma2(wn_[4*i+j], v1.v[j], A5[j]);                     \
            }                                                                    \
        }                                                                        \
        /* sub-chain tree (depth 8 chains + 2 HADD2) then fp32 finish */         \
        float fr0, fz0, fn0, fr1, fz1, fn1;                                      \
        {                                                                        \
            __nv_bfloat162 s; float2 f;                                          \
            s = __hadd2(__hadd2(A0[0],A0[1]), __hadd2(A0[2],A0[3]));             \
            f = __bfloat1622float2(s); fr0 = f.x + f.y;                          \
            s = __hadd2(__hadd2(A1[0],A1[1]), __hadd2(A1[2],A1[3]));             \
            f = __bfloat1622float2(s); fz0 = f.x + f.y;                          \
            s = __hadd2(__hadd2(A2[0],A2[1]), __hadd2(A2[2],A2[3]));             \
            f = __bfloat1622float2(s); fn0 = f.x + f.y;                          \
            s = __hadd2(__hadd2(A3[0],A3[1]), __hadd2(A3[2],A3[3]));             \
            f = __bfloat1622float2(s); fr1 = f.x + f.y;                          \
            s = __hadd2(__hadd2(A4[0],A4[1]), __hadd2(A4[2],A4[3]));             \
            f = __bfloat1622float2(s); fz1 = f.x + f.y;                          \
            s = __hadd2(__hadd2(A5[0],A5[1]), __hadd2(A5[2],A5[3]));             \
            f = __bfloat1622float2(s); fn1 = f.x + f.y;                          \
        }                                                                        \
        /* 3-shfl exchange: keep batch==half, send the other */                  \
        float sr = half ? fr0 : fr1;                                             \
        float sz = half ? fz0 : fz1;                                             \
        float sn = half ? fn0 : fn1;                                             \
        float rr = __shfl_xor_sync(0xffffffffu, sr, 1);                          \
        float rz = __shfl_xor_sync(0xffffffffu, sz, 1);                          \
        float rn = __shfl_xor_sync(0xffffffffu, sn, 1);                          \
        float d_r = (half ? fr1 : fr0) + rr;                                     \
        float d_z = (half ? fz1 : fz0) + rz;                                     \
        float d_n = (half ? fn1 : fn0) + rn;                                     \
        /* gates fp32, single-MUFU each */                                       \
        float r  = fsig(gir + d_r);                                              \
        float z  = fsig(giz + d_z);                                              \
        float n  = tanha(gin + r * (d_n + Cnh));                                 \
        hprev = n + z * (hprev - n);                                             \
        h_sh[(RB) ^ 1][half][hwr] = __float2bfloat16(hprev);                     \
        __syncthreads();                                                         \
    } while (0)

    for (int s = 0; s < SEQ; s += 2) {
        STEP(0, s);
        STEP(1, s + 1);
    }
    #undef STEP

    // ---- fused fc1: out[b] = relu(hT) . w_fc + b_fc (fp32 h state) ----
    red_sh[half * HID + u] = fmaxf(hprev, 0.0f) * w_fc[u];
    __syncthreads();
    if (t < BPC) {
        float acc = b_fc[0];
        #pragma unroll 8
        for (int k = 0; k < HID; k++)
            acc += red_sh[t * HID + k];
        out[b0 + t] = acc;
    }
}

extern "C" void kernel_launch(void* const* d_in, const int* in_sizes, int n_in,
                              void* d_out, int out_size) {
    const float* x    = (const float*)d_in[0];
    const float* w_ih = (const float*)d_in[1];
    const float* w_hh = (const float*)d_in[2];
    const float* b_ih = (const float*)d_in[3];
    const float* b_hh = (const float*)d_in[4];
    const float* w_fc = (const float*)d_in[5];
    const float* b_fc = (const float*)d_in[6];
    float* out = (float*)d_out;

    gru_fused_kernel<<<NCTA, NTHR>>>(x, w_ih, w_hh, b_ih, b_hh, w_fc, b_fc, out);
}